// round 2
// baseline (speedup 1.0000x reference)
#include <cuda_runtime.h>
#include <math.h>

#define NTOK 16384
#define DM   1024
#define FFDIM 2816

// Scratch (device globals -- no allocation allowed)
__device__ float g_z[NTOK * DM];        // rmsnorm output, 64 MB
__device__ float g_bx[NTOK * 64];       // low-rank intermediates (dual, stride 64)
__device__ float g_bx3[NTOK * 32];      // low-rank intermediate (single, stride 32)
__device__ float g_ff[NTOK * FFDIM];    // ff activations, 180 MB

// ---------------------------------------------------------------------------
__global__ __launch_bounds__(256) void copy4_kernel(const float4* __restrict__ src,
                                                    float4* __restrict__ dst, int n4) {
    int i = blockIdx.x * 256 + threadIdx.x;
    if (i < n4) dst[i] = src[i];
}

// z = h * rsqrt(mean(h^2) + eps); one block per row, 256 threads, 1 float4/thread
__global__ __launch_bounds__(256) void rmsnorm_kernel(const float* __restrict__ h) {
    int row = blockIdx.x;
    const float4* hv = (const float4*)(h + row * DM);
    float4 v = hv[threadIdx.x];
    float ss = v.x * v.x + v.y * v.y + v.z * v.z + v.w * v.w;
#pragma unroll
    for (int o = 16; o; o >>= 1) ss += __shfl_xor_sync(0xffffffffu, ss, o);
    __shared__ float wsum[8];
    int wid = threadIdx.x >> 5, lane = threadIdx.x & 31;
    if (lane == 0) wsum[wid] = ss;
    __syncthreads();
    if (threadIdx.x == 0) {
        float t = 0.f;
#pragma unroll
        for (int i = 0; i < 8; i++) t += wsum[i];
        wsum[0] = t;
    }
    __syncthreads();
    float ms = wsum[0] * (1.0f / DM) + 1.1920929e-07f;
    float r = rsqrtf(ms);
    r = r * (1.5f - 0.5f * ms * r * r);   // Newton refine
    float4 o4 = make_float4(v.x * r, v.y * r, v.z * r, v.w * r);
    ((float4*)(g_z + row * DM))[threadIdx.x] = o4;
}

// ---------------------------------------------------------------------------
// bx[t, n] = sum_k B[n,k] * X[t,k]
// mode 0: X = combined(z, shifted z), logical K=2048. mode 1: X = z. mode 2: X = ff.
// NOUT=64: n<32 -> B0 rows, n>=32 -> B1 rows; writes g_bx. NOUT=32: B0 only; writes g_bx3.
template <int NOUT>
__global__ __launch_bounds__(256) void bx_kernel(const float* __restrict__ B0,
                                                 const float* __restrict__ B1,
                                                 int K, int mode) {
    __shared__ float Xs[32][33];
    __shared__ float Bs[NOUT][33];
    const int JP = NOUT / 8;
    int t0 = blockIdx.x * 32;
    int tid = threadIdx.x;
    int tt = tid & 31, ng = tid >> 5;
    float acc[JP];
#pragma unroll
    for (int j = 0; j < JP; j++) acc[j] = 0.f;

    for (int kc = 0; kc < K; kc += 32) {
        for (int idx = tid; idx < 32 * 32; idx += 256) {
            int to = idx >> 5, kk = idx & 31;
            int t = t0 + to, k = kc + kk;
            float v;
            if (mode == 0) {
                if (k < DM) v = g_z[t * DM + k];
                else v = ((t & 2047) == 0) ? 0.f : g_z[(t - 1) * DM + (k - DM)];
            } else if (mode == 1) {
                v = g_z[t * DM + k];
            } else {
                v = g_ff[t * FFDIM + k];
            }
            Xs[to][kk] = v;
        }
        for (int idx = tid; idx < NOUT * 32; idx += 256) {
            int n = idx >> 5, kk = idx & 31;
            int k = kc + kk;
            Bs[n][kk] = (n < 32) ? B0[n * K + k] : B1[(n - 32) * K + k];
        }
        __syncthreads();
        int nb = ng * JP;
#pragma unroll
        for (int kk = 0; kk < 32; kk++) {
            float xv = Xs[tt][kk];
#pragma unroll
            for (int j = 0; j < JP; j++) acc[j] += Bs[nb + j][kk] * xv;
        }
        __syncthreads();
    }
    int t = t0 + tt;
    int nb = ng * JP;
    float* out = (NOUT == 64) ? g_bx : g_bx3;
#pragma unroll
    for (int j = 0; j < JP; j++) out[t * NOUT + nb + j] = acc[j];
}

// ---------------------------------------------------------------------------
// Fused gate/update lslinear + gated residual.
// grid (NTOK/64, 8). Block b of 8: outputs o in [b*128,(b+1)*128), inputs are a
// 256-wide slice of z (b<4) or shifted z (b>=4). Epilogue: h += sigmoid(g)*u.
__global__ __launch_bounds__(256) void gate_update_kernel(
    const float* __restrict__ Wg, const float* __restrict__ Wu,
    const float* __restrict__ Ag, const float* __restrict__ Au,
    float* __restrict__ h) {
    __shared__ float pool[12288];          // 48 KB
    float* Xs  = pool;                     // [64][17]
    float* WgS = pool + 1088;              // [16][128]
    float* WuS = pool + 3136;              // [16][128]

    int b = blockIdx.y;
    int t0 = blockIdx.x * 64;
    int tid = threadIdx.x;
    int tx = tid & 31;                     // float4 output column
    int ty = tid >> 5;                     // token group (8 tokens each)
    float accg[8][4] = {};
    float accu[8][4] = {};

    int xoff = (b < 4) ? b * 256 : (b - 4) * 256;
    bool shifted = (b >= 4);

    for (int kc = 0; kc < 256; kc += 16) {
#pragma unroll
        for (int l = 0; l < 4; l++) {
            int idx = tid + l * 256;
            int to = idx >> 4, kk = idx & 15;
            int t = t0 + to;
            float v;
            if (!shifted) v = g_z[t * DM + xoff + kc + kk];
            else v = ((t & 2047) == 0) ? 0.f : g_z[(t - 1) * DM + xoff + kc + kk];
            Xs[to * 17 + kk] = v;
        }
#pragma unroll
        for (int l = 0; l < 2; l++) {
            int idx = tid + l * 256;
            int o = idx >> 2, k4 = idx & 3;
            float4 wg4 = *(const float4*)(Wg + (b * 128 + o) * 256 + kc + k4 * 4);
            float4 wu4 = *(const float4*)(Wu + (b * 128 + o) * 256 + kc + k4 * 4);
            int kk = k4 * 4;
            WgS[(kk + 0) * 128 + o] = wg4.x; WgS[(kk + 1) * 128 + o] = wg4.y;
            WgS[(kk + 2) * 128 + o] = wg4.z; WgS[(kk + 3) * 128 + o] = wg4.w;
            WuS[(kk + 0) * 128 + o] = wu4.x; WuS[(kk + 1) * 128 + o] = wu4.y;
            WuS[(kk + 2) * 128 + o] = wu4.z; WuS[(kk + 3) * 128 + o] = wu4.w;
        }
        __syncthreads();
#pragma unroll
        for (int kk = 0; kk < 16; kk++) {
            float4 wg = *(const float4*)(WgS + kk * 128 + tx * 4);
            float4 wu = *(const float4*)(WuS + kk * 128 + tx * 4);
#pragma unroll
            for (int ti = 0; ti < 8; ti++) {
                float xv = Xs[(ty * 8 + ti) * 17 + kk];
                accg[ti][0] += wg.x * xv; accg[ti][1] += wg.y * xv;
                accg[ti][2] += wg.z * xv; accg[ti][3] += wg.w * xv;
                accu[ti][0] += wu.x * xv; accu[ti][1] += wu.y * xv;
                accu[ti][2] += wu.z * xv; accu[ti][3] += wu.w * xv;
            }
        }
        __syncthreads();
    }

    // Low-rank: +A @ bx (K=32). Reuse smem pool.
    float* AgS = pool;          // [32][128]
    float* AuS = pool + 4096;   // [32][128]
    float* bxS = pool + 8192;   // [64][64]
#pragma unroll
    for (int l = 0; l < 16; l++) {
        int idx = tid + l * 256;
        int r = idx >> 7, o = idx & 127;
        AgS[r * 128 + o] = Ag[(b * 128 + o) * 32 + r];
        AuS[r * 128 + o] = Au[(b * 128 + o) * 32 + r];
    }
#pragma unroll
    for (int l = 0; l < 16; l++) {
        int idx = tid + l * 256;
        int to = idx >> 6, r = idx & 63;
        bxS[to * 64 + r] = g_bx[(t0 + to) * 64 + r];
    }
    __syncthreads();
#pragma unroll
    for (int r = 0; r < 32; r++) {
        float4 ag = *(const float4*)(AgS + r * 128 + tx * 4);
        float4 au = *(const float4*)(AuS + r * 128 + tx * 4);
#pragma unroll
        for (int ti = 0; ti < 8; ti++) {
            float bf = bxS[(ty * 8 + ti) * 64 + r];
            float bu = bxS[(ty * 8 + ti) * 64 + 32 + r];
            accg[ti][0] += ag.x * bf; accg[ti][1] += ag.y * bf;
            accg[ti][2] += ag.z * bf; accg[ti][3] += ag.w * bf;
            accu[ti][0] += au.x * bu; accu[ti][1] += au.y * bu;
            accu[ti][2] += au.z * bu; accu[ti][3] += au.w * bu;
        }
    }
    // Epilogue: h += sigmoid(g) * u
#pragma unroll
    for (int ti = 0; ti < 8; ti++) {
        int t = t0 + ty * 8 + ti;
        float4* hp = (float4*)(h + t * DM + b * 128 + tx * 4);
        float4 hv = *hp;
        hv.x += accu[ti][0] / (1.f + __expf(-accg[ti][0]));
        hv.y += accu[ti][1] / (1.f + __expf(-accg[ti][1]));
        hv.z += accu[ti][2] / (1.f + __expf(-accg[ti][2]));
        hv.w += accu[ti][3] / (1.f + __expf(-accg[ti][3]));
        *hp = hv;
    }
}

// ---------------------------------------------------------------------------
// ff = silu(lslinear(z, ffg)) * lslinear(z, fff).  bi=128, 352 outs/block.
// grid (NTOK/64, 8, 6): blockIdx.z tiles the 352 outputs in chunks of 64.
__global__ __launch_bounds__(256) void ff_kernel(
    const float* __restrict__ Wa, const float* __restrict__ Wc,
    const float* __restrict__ Aa, const float* __restrict__ Ac) {
    __shared__ float pool[8192];           // 32 KB
    float* Xs  = pool;                     // [64][17]
    float* WaS = pool + 1088;              // [16][64]
    float* WcS = pool + 2112;              // [16][64]

    int b = blockIdx.y;
    int ot = blockIdx.z * 64;
    int t0 = blockIdx.x * 64;
    int tid = threadIdx.x;
    int tx = tid & 15;
    int ty = tid >> 4;
    float acca[4][4] = {};
    float accc[4][4] = {};

    for (int kc = 0; kc < 128; kc += 16) {
#pragma unroll
        for (int l = 0; l < 4; l++) {
            int idx = tid + l * 256;
            int to = idx >> 4, kk = idx & 15;
            Xs[to * 17 + kk] = g_z[(t0 + to) * DM + b * 128 + kc + kk];
        }
        {
            int o = tid >> 2, k4 = tid & 3;
            float4 wa4 = make_float4(0.f, 0.f, 0.f, 0.f);
            float4 wc4 = wa4;
            if (ot + o < 352) {
                int gr = b * 352 + ot + o;
                wa4 = *(const float4*)(Wa + gr * 128 + kc + k4 * 4);
                wc4 = *(const float4*)(Wc + gr * 128 + kc + k4 * 4);
            }
            int kk = k4 * 4;
            WaS[(kk + 0) * 64 + o] = wa4.x; WaS[(kk + 1) * 64 + o] = wa4.y;
            WaS[(kk + 2) * 64 + o] = wa4.z; WaS[(kk + 3) * 64 + o] = wa4.w;
            WcS[(kk + 0) * 64 + o] = wc4.x; WcS[(kk + 1) * 64 + o] = wc4.y;
            WcS[(kk + 2) * 64 + o] = wc4.z; WcS[(kk + 3) * 64 + o] = wc4.w;
        }
        __syncthreads();
#pragma unroll
        for (int kk = 0; kk < 16; kk++) {
            float4 wa = *(const float4*)(WaS + kk * 64 + tx * 4);
            float4 wc = *(const float4*)(WcS + kk * 64 + tx * 4);
#pragma unroll
            for (int ti = 0; ti < 4; ti++) {
                float xv = Xs[(ty * 4 + ti) * 17 + kk];
                acca[ti][0] += wa.x * xv; acca[ti][1] += wa.y * xv;
                acca[ti][2] += wa.z * xv; acca[ti][3] += wa.w * xv;
                accc[ti][0] += wc.x * xv; accc[ti][1] += wc.y * xv;
                accc[ti][2] += wc.z * xv; accc[ti][3] += wc.w * xv;
            }
        }
        __syncthreads();
    }

    float* AaS = pool;          // [32][64]
    float* AcS = pool + 2048;   // [32][64]
    float* bxS = pool + 4096;   // [64][64]
#pragma unroll
    for (int l = 0; l < 8; l++) {
        int idx = tid + l * 256;
        int r = idx >> 6, o = idx & 63;
        float va = 0.f, vc = 0.f;
        if (ot + o < 352) {
            int gr = b * 352 + ot + o;
            va = Aa[gr * 32 + r];
            vc = Ac[gr * 32 + r];
        }
        AaS[r * 64 + o] = va;
        AcS[r * 64 + o] = vc;
    }
#pragma unroll
    for (int l = 0; l < 16; l++) {
        int idx = tid + l * 256;
        int to = idx >> 6, r = idx & 63;
        bxS[to * 64 + r] = g_bx[(t0 + to) * 64 + r];
    }
    __syncthreads();
#pragma unroll
    for (int r = 0; r < 32; r++) {
        float4 aa = *(const float4*)(AaS + r * 64 + tx * 4);
        float4 ac = *(const float4*)(AcS + r * 64 + tx * 4);
#pragma unroll
        for (int ti = 0; ti < 4; ti++) {
            float ba = bxS[(ty * 4 + ti) * 64 + r];
            float bc = bxS[(ty * 4 + ti) * 64 + 32 + r];
            acca[ti][0] += aa.x * ba; acca[ti][1] += aa.y * ba;
            acca[ti][2] += aa.z * ba; acca[ti][3] += aa.w * ba;
            accc[ti][0] += ac.x * bc; accc[ti][1] += ac.y * bc;
            accc[ti][2] += ac.z * bc; accc[ti][3] += ac.w * bc;
        }
    }
    if (ot + tx * 4 < 352) {
#pragma unroll
        for (int ti = 0; ti < 4; ti++) {
            int t = t0 + ty * 4 + ti;
            float4 o4;
            float a0 = acca[ti][0], a1 = acca[ti][1], a2 = acca[ti][2], a3 = acca[ti][3];
            o4.x = (a0 / (1.f + __expf(-a0))) * accc[ti][0];
            o4.y = (a1 / (1.f + __expf(-a1))) * accc[ti][1];
            o4.z = (a2 / (1.f + __expf(-a2))) * accc[ti][2];
            o4.w = (a3 / (1.f + __expf(-a3))) * accc[ti][3];
            *(float4*)(g_ff + t * FFDIM + b * 352 + ot + tx * 4) = o4;
        }
    }
}

// ---------------------------------------------------------------------------
// out += lslinear(ff, ffp).  bi=352, 128 outs/block.  grid (NTOK/64, 8).
__global__ __launch_bounds__(256) void ffp_kernel(
    const float* __restrict__ W, const float* __restrict__ A,
    float* __restrict__ out) {
    __shared__ float pool[6144];           // 24 KB
    float* Xs = pool;                      // [64][17]
    float* WS = pool + 1088;               // [16][128]

    int b = blockIdx.y;
    int t0 = blockIdx.x * 64;
    int tid = threadIdx.x;
    int tx = tid & 31, ty = tid >> 5;
    float acc[8][4] = {};

    for (int kc = 0; kc < 352; kc += 16) {
#pragma unroll
        for (int l = 0; l < 4; l++) {
            int idx = tid + l * 256;
            int to = idx >> 4, kk = idx & 15;
            Xs[to * 17 + kk] = g_ff[(t0 + to) * FFDIM + b * 352 + kc + kk];
        }
#pragma unroll
        for (int l = 0; l < 2; l++) {
            int idx = tid + l * 256;
            int o = idx >> 2, k4 = idx & 3;
            float4 w4 = *(const float4*)(W + (b * 128 + o) * 352 + kc + k4 * 4);
            int kk = k4 * 4;
            WS[(kk + 0) * 128 + o] = w4.x; WS[(kk + 1) * 128 + o] = w4.y;
            WS[(kk + 2) * 128 + o] = w4.z; WS[(kk + 3) * 128 + o] = w4.w;
        }
        __syncthreads();
#pragma unroll
        for (int kk = 0; kk < 16; kk++) {
            float4 w = *(const float4*)(WS + kk * 128 + tx * 4);
#pragma unroll
            for (int ti = 0; ti < 8; ti++) {
                float xv = Xs[(ty * 8 + ti) * 17 + kk];
                acc[ti][0] += w.x * xv; acc[ti][1] += w.y * xv;
                acc[ti][2] += w.z * xv; acc[ti][3] += w.w * xv;
            }
        }
        __syncthreads();
    }

    float* AS  = pool;          // [32][128]
    float* bxS = pool + 4096;   // [64][32]
#pragma unroll
    for (int l = 0; l < 16; l++) {
        int idx = tid + l * 256;
        int r = idx >> 7, o = idx & 127;
        AS[r * 128 + o] = A[(b * 128 + o) * 32 + r];
    }
#pragma unroll
    for (int l = 0; l < 8; l++) {
        int idx = tid + l * 256;
        int to = idx >> 5, r = idx & 31;
        bxS[to * 32 + r] = g_bx3[(t0 + to) * 32 + r];
    }
    __syncthreads();
#pragma unroll
    for (int r = 0; r < 32; r++) {
        float4 a4 = *(const float4*)(AS + r * 128 + tx * 4);
#pragma unroll
        for (int ti = 0; ti < 8; ti++) {
            float bb = bxS[(ty * 8 + ti) * 32 + r];
            acc[ti][0] += a4.x * bb; acc[ti][1] += a4.y * bb;
            acc[ti][2] += a4.z * bb; acc[ti][3] += a4.w * bb;
        }
    }
#pragma unroll
    for (int ti = 0; ti < 8; ti++) {
        int t = t0 + ty * 8 + ti;
        float4* op = (float4*)(out + t * DM + b * 128 + tx * 4);
        float4 v = *op;
        v.x += acc[ti][0]; v.y += acc[ti][1];
        v.z += acc[ti][2]; v.w += acc[ti][3];
        *op = v;
    }
}

// ---------------------------------------------------------------------------
extern "C" void kernel_launch(void* const* d_in, const int* in_sizes, int n_in,
                              void* d_out, int out_size) {
    (void)in_sizes; (void)n_in; (void)out_size;
    const float* x     = (const float*)d_in[0];
    const float* fg_W  = (const float*)d_in[1];
    const float* fg_A  = (const float*)d_in[2];
    const float* fg_B  = (const float*)d_in[3];
    const float* gu_W  = (const float*)d_in[4];
    const float* gu_A  = (const float*)d_in[5];
    const float* gu_B  = (const float*)d_in[6];
    const float* ffg_W = (const float*)d_in[7];
    const float* ffg_A = (const float*)d_in[8];
    const float* ffg_B = (const float*)d_in[9];
    const float* fff_W = (const float*)d_in[10];
    const float* fff_A = (const float*)d_in[11];
    const float* fff_B = (const float*)d_in[12];
    const float* ffp_W = (const float*)d_in[13];
    const float* ffp_A = (const float*)d_in[14];
    const float* ffp_B = (const float*)d_in[15];
    float* h = (float*)d_out;

    // h = x
    copy4_kernel<<<(NTOK * DM / 4 + 255) / 256, 256>>>((const float4*)x, (float4*)h,
                                                       NTOK * DM / 4);
    for (int it = 0; it < 4; ++it) {
        rmsnorm_kernel<<<NTOK, 256>>>(h);
        bx_kernel<64><<<NTOK / 32, 256>>>(fg_B, gu_B, 2048, 0);
        gate_update_kernel<<<dim3(NTOK / 64, 8), 256>>>(fg_W, gu_W, fg_A, gu_A, h);
    }
    rmsnorm_kernel<<<NTOK, 256>>>(h);
    bx_kernel<64><<<NTOK / 32, 256>>>(ffg_B, fff_B, 1024, 1);
    ff_kernel<<<dim3(NTOK / 64, 8, 6), 256>>>(ffg_W, fff_W, ffg_A, fff_A);
    bx_kernel<32><<<NTOK / 32, 256>>>(ffp_B, ffp_B, 2816, 2);
    ffp_kernel<<<dim3(NTOK / 64, 8), 256>>>(ffp_W, ffp_A, h);
}

// round 3
// speedup vs baseline: 2.1195x; 2.1195x over previous
#include <cuda_runtime.h>
#include <math.h>
#include <stdint.h>

#define NTOK 16384
#define DM   1024
#define FFDIM 2816

// Scratch (device globals -- no allocation allowed)
__device__ float g_z[NTOK * DM];        // rmsnorm output
__device__ float g_bx[NTOK * 64];       // low-rank intermediates (dual, stride 64)
__device__ float g_bx3[NTOK * 32];      // low-rank intermediate (single, stride 32)
__device__ float g_ff[NTOK * FFDIM];    // ff activations

// ---------------------------------------------------------------------------
__device__ __forceinline__ uint32_t f2t(float f) {
    uint32_t u;
    asm("cvt.rna.tf32.f32 %0, %1;" : "=r"(u) : "f"(f));
    return u;
}

__device__ __forceinline__ void mma_tf32(float* c, const uint32_t* a, const uint32_t* b) {
    asm volatile(
        "mma.sync.aligned.m16n8k8.row.col.f32.tf32.tf32.f32 "
        "{%0,%1,%2,%3}, {%4,%5,%6,%7}, {%8,%9}, {%0,%1,%2,%3};\n"
        : "+f"(c[0]), "+f"(c[1]), "+f"(c[2]), "+f"(c[3])
        : "r"(a[0]), "r"(a[1]), "r"(a[2]), "r"(a[3]), "r"(b[0]), "r"(b[1]));
}

__device__ __forceinline__ float sigmoidf_(float x) {
    return 1.0f / (1.0f + __expf(-x));
}

// ---------------------------------------------------------------------------
__global__ __launch_bounds__(256) void copy4_kernel(const float4* __restrict__ src,
                                                    float4* __restrict__ dst, int n4) {
    int i = blockIdx.x * 256 + threadIdx.x;
    if (i < n4) dst[i] = src[i];
}

// z = h * rsqrt(mean(h^2) + eps); one block per row
__global__ __launch_bounds__(256) void rmsnorm_kernel(const float* __restrict__ h) {
    int row = blockIdx.x;
    const float4* hv = (const float4*)(h + row * DM);
    float4 v = hv[threadIdx.x];
    float ss = v.x * v.x + v.y * v.y + v.z * v.z + v.w * v.w;
#pragma unroll
    for (int o = 16; o; o >>= 1) ss += __shfl_xor_sync(0xffffffffu, ss, o);
    __shared__ float wsum[8];
    int wid = threadIdx.x >> 5, lane = threadIdx.x & 31;
    if (lane == 0) wsum[wid] = ss;
    __syncthreads();
    if (threadIdx.x == 0) {
        float t = 0.f;
#pragma unroll
        for (int i = 0; i < 8; i++) t += wsum[i];
        wsum[0] = t;
    }
    __syncthreads();
    float ms = wsum[0] * (1.0f / DM) + 1.1920929e-07f;
    float r = rsqrtf(ms);
    r = r * (1.5f - 0.5f * ms * r * r);   // Newton refine
    float4 o4 = make_float4(v.x * r, v.y * r, v.z * r, v.w * r);
    ((float4*)(g_z + row * DM))[threadIdx.x] = o4;
}

// ---------------------------------------------------------------------------
// bx[t, n] = sum_k B[n,k] * X[t,k]   (tf32 MMA)
// mode 0: X = combined(z, shifted z), K=2048. mode 1: X = z (K=1024). mode 2: X = ff (K=2816).
// NOUT=64: rows<32 from B0, >=32 from B1 -> g_bx. NOUT=32: B0 only -> g_bx3.
template <int NOUT>
__global__ __launch_bounds__(256) void bx_mma(const float* __restrict__ B0,
                                              const float* __restrict__ B1,
                                              int K, int mode) {
    __shared__ uint32_t Xs[128 * 36];
    __shared__ uint32_t Bs[NOUT * 36];
    const int t0 = blockIdx.x * 128;
    const int tid = threadIdx.x;
    const int warp = tid >> 5, lane = tid & 31;
    const int g = lane >> 2, c = lane & 3;
    const int MT = (NOUT == 64) ? 2 : 1;
    const int wm = (NOUT == 64) ? (warp >> 1) : warp;     // m base = wm * (16*MT)
    const int wn = (NOUT == 64) ? (warp & 1) : 0;         // n base = wn * 32

    float acc[2][4][4];
#pragma unroll
    for (int mt = 0; mt < 2; mt++)
#pragma unroll
        for (int nf = 0; nf < 4; nf++)
#pragma unroll
            for (int i = 0; i < 4; i++) acc[mt][nf][i] = 0.f;

    for (int kc = 0; kc < K; kc += 32) {
        // X tile: 128 rows x 32 cols, 8 float4 per row -> 1024 f4 -> 4/thread
#pragma unroll
        for (int l = 0; l < 4; l++) {
            int idx = tid + l * 256;
            int to = idx >> 3, c4 = (idx & 7) * 4;
            int t = t0 + to, k = kc + c4;
            float4 v;
            if (mode == 0) {
                if (k < DM) v = *(const float4*)(g_z + t * DM + k);
                else if ((t & 2047) == 0) v = make_float4(0.f, 0.f, 0.f, 0.f);
                else v = *(const float4*)(g_z + (t - 1) * DM + (k - DM));
            } else if (mode == 1) {
                v = *(const float4*)(g_z + t * DM + k);
            } else {
                v = *(const float4*)(g_ff + t * FFDIM + k);
            }
            uint32_t* xp = Xs + to * 36 + c4;
            xp[0] = f2t(v.x); xp[1] = f2t(v.y); xp[2] = f2t(v.z); xp[3] = f2t(v.w);
        }
        // B tile: NOUT rows x 32 cols
#pragma unroll
        for (int l = 0; l < NOUT / 32; l++) {
            int idx = tid + l * 256;
            int o = idx >> 3, c4 = (idx & 7) * 4;
            int k = kc + c4;
            float4 v = (o < 32) ? *(const float4*)(B0 + o * K + k)
                                : *(const float4*)(B1 + (o - 32) * K + k);
            uint32_t* bp = Bs + o * 36 + c4;
            bp[0] = f2t(v.x); bp[1] = f2t(v.y); bp[2] = f2t(v.z); bp[3] = f2t(v.w);
        }
        __syncthreads();
#pragma unroll
        for (int ks = 0; ks < 4; ks++) {
            int k0 = ks * 8;
            uint32_t a[2][4];
#pragma unroll
            for (int mt = 0; mt < MT; mt++) {
                int r = wm * (16 * MT) + mt * 16;
                a[mt][0] = Xs[(r + g) * 36 + k0 + c];
                a[mt][1] = Xs[(r + 8 + g) * 36 + k0 + c];
                a[mt][2] = Xs[(r + g) * 36 + k0 + 4 + c];
                a[mt][3] = Xs[(r + 8 + g) * 36 + k0 + 4 + c];
            }
#pragma unroll
            for (int nf = 0; nf < 4; nf++) {
                int col = wn * 32 + nf * 8 + g;
                uint32_t bb[2] = {Bs[col * 36 + k0 + c], Bs[col * 36 + k0 + 4 + c]};
#pragma unroll
                for (int mt = 0; mt < MT; mt++) mma_tf32(acc[mt][nf], a[mt], bb);
            }
        }
        __syncthreads();
    }
    float* out = (NOUT == 64) ? g_bx : g_bx3;
#pragma unroll
    for (int mt = 0; mt < MT; mt++) {
#pragma unroll
        for (int nf = 0; nf < 4; nf++) {
            int r0 = t0 + wm * (16 * MT) + mt * 16 + g;
            int col = wn * 32 + nf * 8 + c * 2;
            *(float2*)(out + r0 * NOUT + col) = make_float2(acc[mt][nf][0], acc[mt][nf][1]);
            *(float2*)(out + (r0 + 8) * NOUT + col) = make_float2(acc[mt][nf][2], acc[mt][nf][3]);
        }
    }
}

// ---------------------------------------------------------------------------
// Fused gate/update lslinear + low-rank + gated residual.  grid (NTOK/64, 8).
__global__ __launch_bounds__(256) void gate_update_mma(
    const float* __restrict__ Wg, const float* __restrict__ Wu,
    const float* __restrict__ Ag, const float* __restrict__ Au,
    float* __restrict__ h) {
    __shared__ uint32_t Xs[64 * 36];
    __shared__ uint32_t WgS[128 * 36];
    __shared__ uint32_t WuS[128 * 36];
    const int b = blockIdx.y;
    const int t0 = blockIdx.x * 64;
    const int tid = threadIdx.x;
    const int warp = tid >> 5, lane = tid & 31;
    const int wm = warp >> 2, wn = warp & 3;   // wm: 0..1 (m32), wn: 0..3 (n32)
    const int g = lane >> 2, c = lane & 3;
    const int xoff = (b < 4) ? b * 256 : (b - 4) * 256;
    const bool sh = (b >= 4);

    float accg[2][4][4], accu[2][4][4];
#pragma unroll
    for (int mt = 0; mt < 2; mt++)
#pragma unroll
        for (int nf = 0; nf < 4; nf++)
#pragma unroll
            for (int i = 0; i < 4; i++) { accg[mt][nf][i] = 0.f; accu[mt][nf][i] = 0.f; }

    for (int kc = 0; kc < 256; kc += 32) {
        // X tile 64x32 -> 512 f4 -> 2/thread
#pragma unroll
        for (int l = 0; l < 2; l++) {
            int idx = tid + l * 256;
            int to = idx >> 3, c4 = (idx & 7) * 4;
            int t = t0 + to;
            float4 v;
            if (!sh) v = *(const float4*)(g_z + t * DM + xoff + kc + c4);
            else if ((t & 2047) == 0) v = make_float4(0.f, 0.f, 0.f, 0.f);
            else v = *(const float4*)(g_z + (t - 1) * DM + xoff + kc + c4);
            uint32_t* xp = Xs + to * 36 + c4;
            xp[0] = f2t(v.x); xp[1] = f2t(v.y); xp[2] = f2t(v.z); xp[3] = f2t(v.w);
        }
        // W tiles 128x32 each -> 1024 f4 -> 4/thread each
#pragma unroll
        for (int l = 0; l < 4; l++) {
            int idx = tid + l * 256;
            int o = idx >> 3, c4 = (idx & 7) * 4;
            const float* base = Wg + (b * 128 + o) * 256 + kc + c4;
            float4 vg = *(const float4*)base;
            float4 vu = *(const float4*)(Wu + (b * 128 + o) * 256 + kc + c4);
            uint32_t* pg = WgS + o * 36 + c4;
            uint32_t* pu = WuS + o * 36 + c4;
            pg[0] = f2t(vg.x); pg[1] = f2t(vg.y); pg[2] = f2t(vg.z); pg[3] = f2t(vg.w);
            pu[0] = f2t(vu.x); pu[1] = f2t(vu.y); pu[2] = f2t(vu.z); pu[3] = f2t(vu.w);
        }
        __syncthreads();
#pragma unroll
        for (int ks = 0; ks < 4; ks++) {
            int k0 = ks * 8;
            uint32_t a[2][4];
#pragma unroll
            for (int mt = 0; mt < 2; mt++) {
                int r = wm * 32 + mt * 16;
                a[mt][0] = Xs[(r + g) * 36 + k0 + c];
                a[mt][1] = Xs[(r + 8 + g) * 36 + k0 + c];
                a[mt][2] = Xs[(r + g) * 36 + k0 + 4 + c];
                a[mt][3] = Xs[(r + 8 + g) * 36 + k0 + 4 + c];
            }
#pragma unroll
            for (int nf = 0; nf < 4; nf++) {
                int col = wn * 32 + nf * 8 + g;
                uint32_t bg[2] = {WgS[col * 36 + k0 + c], WgS[col * 36 + k0 + 4 + c]};
                uint32_t bu[2] = {WuS[col * 36 + k0 + c], WuS[col * 36 + k0 + 4 + c]};
#pragma unroll
                for (int mt = 0; mt < 2; mt++) {
                    mma_tf32(accg[mt][nf], a[mt], bg);
                    mma_tf32(accu[mt][nf], a[mt], bu);
                }
            }
        }
        __syncthreads();
    }

    // Low-rank rank-32 term straight from global (L2-resident)
#pragma unroll
    for (int ks = 0; ks < 4; ks++) {
        int k0 = ks * 8;
        uint32_t ag[2][4], au[2][4];
#pragma unroll
        for (int mt = 0; mt < 2; mt++) {
            int t = t0 + wm * 32 + mt * 16;
            ag[mt][0] = f2t(g_bx[(t + g) * 64 + k0 + c]);
            ag[mt][1] = f2t(g_bx[(t + 8 + g) * 64 + k0 + c]);
            ag[mt][2] = f2t(g_bx[(t + g) * 64 + k0 + 4 + c]);
            ag[mt][3] = f2t(g_bx[(t + 8 + g) * 64 + k0 + 4 + c]);
            au[mt][0] = f2t(g_bx[(t + g) * 64 + 32 + k0 + c]);
            au[mt][1] = f2t(g_bx[(t + 8 + g) * 64 + 32 + k0 + c]);
            au[mt][2] = f2t(g_bx[(t + g) * 64 + 32 + k0 + 4 + c]);
            au[mt][3] = f2t(g_bx[(t + 8 + g) * 64 + 32 + k0 + 4 + c]);
        }
#pragma unroll
        for (int nf = 0; nf < 4; nf++) {
            int o = b * 128 + wn * 32 + nf * 8 + g;
            uint32_t bg[2] = {f2t(Ag[o * 32 + k0 + c]), f2t(Ag[o * 32 + k0 + 4 + c])};
            uint32_t bu[2] = {f2t(Au[o * 32 + k0 + c]), f2t(Au[o * 32 + k0 + 4 + c])};
#pragma unroll
            for (int mt = 0; mt < 2; mt++) {
                mma_tf32(accg[mt][nf], ag[mt], bg);
                mma_tf32(accu[mt][nf], au[mt], bu);
            }
        }
    }

    // Epilogue: h += sigmoid(g) * u
#pragma unroll
    for (int mt = 0; mt < 2; mt++) {
#pragma unroll
        for (int nf = 0; nf < 4; nf++) {
            int r0 = t0 + wm * 32 + mt * 16 + g;
            int col = b * 128 + wn * 32 + nf * 8 + c * 2;
            float2* p0 = (float2*)(h + r0 * DM + col);
            float2 v0 = *p0;
            v0.x += accu[mt][nf][0] * sigmoidf_(accg[mt][nf][0]);
            v0.y += accu[mt][nf][1] * sigmoidf_(accg[mt][nf][1]);
            *p0 = v0;
            float2* p1 = (float2*)(h + (r0 + 8) * DM + col);
            float2 v1 = *p1;
            v1.x += accu[mt][nf][2] * sigmoidf_(accg[mt][nf][2]);
            v1.y += accu[mt][nf][3] * sigmoidf_(accg[mt][nf][3]);
            *p1 = v1;
        }
    }
}

// ---------------------------------------------------------------------------
// ff = silu(lslinear(z, ffg)) * lslinear(z, fff).  grid (NTOK/64, 8, 3).
__global__ __launch_bounds__(256) void ff_mma(
    const float* __restrict__ Wa, const float* __restrict__ Wc,
    const float* __restrict__ Aa, const float* __restrict__ Ac) {
    __shared__ uint32_t Xs[64 * 36];
    __shared__ uint32_t WaS[128 * 36];
    __shared__ uint32_t WcS[128 * 36];
    const int b = blockIdx.y;
    const int ot = blockIdx.z * 128;
    const int t0 = blockIdx.x * 64;
    const int tid = threadIdx.x;
    const int warp = tid >> 5, lane = tid & 31;
    const int wm = warp >> 2, wn = warp & 3;
    const int g = lane >> 2, c = lane & 3;

    float acca[2][4][4], accc[2][4][4];
#pragma unroll
    for (int mt = 0; mt < 2; mt++)
#pragma unroll
        for (int nf = 0; nf < 4; nf++)
#pragma unroll
            for (int i = 0; i < 4; i++) { acca[mt][nf][i] = 0.f; accc[mt][nf][i] = 0.f; }

    for (int kc = 0; kc < 128; kc += 32) {
#pragma unroll
        for (int l = 0; l < 2; l++) {
            int idx = tid + l * 256;
            int to = idx >> 3, c4 = (idx & 7) * 4;
            float4 v = *(const float4*)(g_z + (t0 + to) * DM + b * 128 + kc + c4);
            uint32_t* xp = Xs + to * 36 + c4;
            xp[0] = f2t(v.x); xp[1] = f2t(v.y); xp[2] = f2t(v.z); xp[3] = f2t(v.w);
        }
#pragma unroll
        for (int l = 0; l < 4; l++) {
            int idx = tid + l * 256;
            int o = idx >> 3, c4 = (idx & 7) * 4;
            int gr = b * 352 + ot + o;
            if (gr > 2815) gr = 2815;   // clamp: garbage rows, never stored
            float4 va = *(const float4*)(Wa + gr * 128 + kc + c4);
            float4 vc = *(const float4*)(Wc + gr * 128 + kc + c4);
            uint32_t* pa = WaS + o * 36 + c4;
            uint32_t* pc = WcS + o * 36 + c4;
            pa[0] = f2t(va.x); pa[1] = f2t(va.y); pa[2] = f2t(va.z); pa[3] = f2t(va.w);
            pc[0] = f2t(vc.x); pc[1] = f2t(vc.y); pc[2] = f2t(vc.z); pc[3] = f2t(vc.w);
        }
        __syncthreads();
#pragma unroll
        for (int ks = 0; ks < 4; ks++) {
            int k0 = ks * 8;
            uint32_t a[2][4];
#pragma unroll
            for (int mt = 0; mt < 2; mt++) {
                int r = wm * 32 + mt * 16;
                a[mt][0] = Xs[(r + g) * 36 + k0 + c];
                a[mt][1] = Xs[(r + 8 + g) * 36 + k0 + c];
                a[mt][2] = Xs[(r + g) * 36 + k0 + 4 + c];
                a[mt][3] = Xs[(r + 8 + g) * 36 + k0 + 4 + c];
            }
#pragma unroll
            for (int nf = 0; nf < 4; nf++) {
                int col = wn * 32 + nf * 8 + g;
                uint32_t ba[2] = {WaS[col * 36 + k0 + c], WaS[col * 36 + k0 + 4 + c]};
                uint32_t bc[2] = {WcS[col * 36 + k0 + c], WcS[col * 36 + k0 + 4 + c]};
#pragma unroll
                for (int mt = 0; mt < 2; mt++) {
                    mma_tf32(acca[mt][nf], a[mt], ba);
                    mma_tf32(accc[mt][nf], a[mt], bc);
                }
            }
        }
        __syncthreads();
    }

    // rank-32 term: a-matrix uses bx[0:32], c-matrix uses bx[32:64]
#pragma unroll
    for (int ks = 0; ks < 4; ks++) {
        int k0 = ks * 8;
        uint32_t aa[2][4], ac[2][4];
#pragma unroll
        for (int mt = 0; mt < 2; mt++) {
            int t = t0 + wm * 32 + mt * 16;
            aa[mt][0] = f2t(g_bx[(t + g) * 64 + k0 + c]);
            aa[mt][1] = f2t(g_bx[(t + 8 + g) * 64 + k0 + c]);
            aa[mt][2] = f2t(g_bx[(t + g) * 64 + k0 + 4 + c]);
            aa[mt][3] = f2t(g_bx[(t + 8 + g) * 64 + k0 + 4 + c]);
            ac[mt][0] = f2t(g_bx[(t + g) * 64 + 32 + k0 + c]);
            ac[mt][1] = f2t(g_bx[(t + 8 + g) * 64 + 32 + k0 + c]);
            ac[mt][2] = f2t(g_bx[(t + g) * 64 + 32 + k0 + 4 + c]);
            ac[mt][3] = f2t(g_bx[(t + 8 + g) * 64 + 32 + k0 + 4 + c]);
        }
#pragma unroll
        for (int nf = 0; nf < 4; nf++) {
            int gr = b * 352 + ot + wn * 32 + nf * 8 + g;
            if (gr > 2815) gr = 2815;
            uint32_t ba[2] = {f2t(Aa[gr * 32 + k0 + c]), f2t(Aa[gr * 32 + k0 + 4 + c])};
            uint32_t bc[2] = {f2t(Ac[gr * 32 + k0 + c]), f2t(Ac[gr * 32 + k0 + 4 + c])};
#pragma unroll
            for (int mt = 0; mt < 2; mt++) {
                mma_tf32(acca[mt][nf], aa[mt], ba);
                mma_tf32(accc[mt][nf], ac[mt], bc);
            }
        }
    }

    // Epilogue: g_ff = silu(a) * c  (masked to 352 cols)
#pragma unroll
    for (int mt = 0; mt < 2; mt++) {
#pragma unroll
        for (int nf = 0; nf < 4; nf++) {
            int col = ot + wn * 32 + nf * 8 + c * 2;
            if (col < 352) {
                int r0 = t0 + wm * 32 + mt * 16 + g;
                float a0 = acca[mt][nf][0], a1 = acca[mt][nf][1];
                float a2 = acca[mt][nf][2], a3 = acca[mt][nf][3];
                float2 v0 = make_float2(a0 * sigmoidf_(a0) * accc[mt][nf][0],
                                        a1 * sigmoidf_(a1) * accc[mt][nf][1]);
                float2 v1 = make_float2(a2 * sigmoidf_(a2) * accc[mt][nf][2],
                                        a3 * sigmoidf_(a3) * accc[mt][nf][3]);
                *(float2*)(g_ff + r0 * FFDIM + b * 352 + col) = v0;
                *(float2*)(g_ff + (r0 + 8) * FFDIM + b * 352 + col) = v1;
            }
        }
    }
}

// ---------------------------------------------------------------------------
// out += lslinear(ff, ffp).  grid (NTOK/64, 8).
__global__ __launch_bounds__(256) void ffp_mma(
    const float* __restrict__ W, const float* __restrict__ A,
    float* __restrict__ out) {
    __shared__ uint32_t Xs[64 * 36];
    __shared__ uint32_t WS[128 * 36];
    const int b = blockIdx.y;
    const int t0 = blockIdx.x * 64;
    const int tid = threadIdx.x;
    const int warp = tid >> 5, lane = tid & 31;
    const int wm = warp >> 2, wn = warp & 3;
    const int g = lane >> 2, c = lane & 3;

    float acc[2][4][4];
#pragma unroll
    for (int mt = 0; mt < 2; mt++)
#pragma unroll
        for (int nf = 0; nf < 4; nf++)
#pragma unroll
            for (int i = 0; i < 4; i++) acc[mt][nf][i] = 0.f;

    for (int kc = 0; kc < 352; kc += 32) {
#pragma unroll
        for (int l = 0; l < 2; l++) {
            int idx = tid + l * 256;
            int to = idx >> 3, c4 = (idx & 7) * 4;
            float4 v = *(const float4*)(g_ff + (t0 + to) * FFDIM + b * 352 + kc + c4);
            uint32_t* xp = Xs + to * 36 + c4;
            xp[0] = f2t(v.x); xp[1] = f2t(v.y); xp[2] = f2t(v.z); xp[3] = f2t(v.w);
        }
#pragma unroll
        for (int l = 0; l < 4; l++) {
            int idx = tid + l * 256;
            int o = idx >> 3, c4 = (idx & 7) * 4;
            float4 v = *(const float4*)(W + (b * 128 + o) * 352 + kc + c4);
            uint32_t* wp = WS + o * 36 + c4;
            wp[0] = f2t(v.x); wp[1] = f2t(v.y); wp[2] = f2t(v.z); wp[3] = f2t(v.w);
        }
        __syncthreads();
#pragma unroll
        for (int ks = 0; ks < 4; ks++) {
            int k0 = ks * 8;
            uint32_t a[2][4];
#pragma unroll
            for (int mt = 0; mt < 2; mt++) {
                int r = wm * 32 + mt * 16;
                a[mt][0] = Xs[(r + g) * 36 + k0 + c];
                a[mt][1] = Xs[(r + 8 + g) * 36 + k0 + c];
                a[mt][2] = Xs[(r + g) * 36 + k0 + 4 + c];
                a[mt][3] = Xs[(r + 8 + g) * 36 + k0 + 4 + c];
            }
#pragma unroll
            for (int nf = 0; nf < 4; nf++) {
                int col = wn * 32 + nf * 8 + g;
                uint32_t bb[2] = {WS[col * 36 + k0 + c], WS[col * 36 + k0 + 4 + c]};
#pragma unroll
                for (int mt = 0; mt < 2; mt++) mma_tf32(acc[mt][nf], a[mt], bb);
            }
        }
        __syncthreads();
    }

    // rank-32 term from g_bx3
#pragma unroll
    for (int ks = 0; ks < 4; ks++) {
        int k0 = ks * 8;
        uint32_t a[2][4];
#pragma unroll
        for (int mt = 0; mt < 2; mt++) {
            int t = t0 + wm * 32 + mt * 16;
            a[mt][0] = f2t(g_bx3[(t + g) * 32 + k0 + c]);
            a[mt][1] = f2t(g_bx3[(t + 8 + g) * 32 + k0 + c]);
            a[mt][2] = f2t(g_bx3[(t + g) * 32 + k0 + 4 + c]);
            a[mt][3] = f2t(g_bx3[(t + 8 + g) * 32 + k0 + 4 + c]);
        }
#pragma unroll
        for (int nf = 0; nf < 4; nf++) {
            int o = b * 128 + wn * 32 + nf * 8 + g;
            uint32_t bb[2] = {f2t(A[o * 32 + k0 + c]), f2t(A[o * 32 + k0 + 4 + c])};
#pragma unroll
            for (int mt = 0; mt < 2; mt++) mma_tf32(acc[mt][nf], a[mt], bb);
        }
    }

    // Epilogue: out += acc
#pragma unroll
    for (int mt = 0; mt < 2; mt++) {
#pragma unroll
        for (int nf = 0; nf < 4; nf++) {
            int r0 = t0 + wm * 32 + mt * 16 + g;
            int col = b * 128 + wn * 32 + nf * 8 + c * 2;
            float2* p0 = (float2*)(out + r0 * DM + col);
            float2 v0 = *p0;
            v0.x += acc[mt][nf][0]; v0.y += acc[mt][nf][1];
            *p0 = v0;
            float2* p1 = (float2*)(out + (r0 + 8) * DM + col);
            float2 v1 = *p1;
            v1.x += acc[mt][nf][2]; v1.y += acc[mt][nf][3];
            *p1 = v1;
        }
    }
}

// ---------------------------------------------------------------------------
extern "C" void kernel_launch(void* const* d_in, const int* in_sizes, int n_in,
                              void* d_out, int out_size) {
    (void)in_sizes; (void)n_in; (void)out_size;
    const float* x     = (const float*)d_in[0];
    const float* fg_W  = (const float*)d_in[1];
    const float* fg_A  = (const float*)d_in[2];
    const float* fg_B  = (const float*)d_in[3];
    const float* gu_W  = (const float*)d_in[4];
    const float* gu_A  = (const float*)d_in[5];
    const float* gu_B  = (const float*)d_in[6];
    const float* ffg_W = (const float*)d_in[7];
    const float* ffg_A = (const float*)d_in[8];
    const float* ffg_B = (const float*)d_in[9];
    const float* fff_W = (const float*)d_in[10];
    const float* fff_A = (const float*)d_in[11];
    const float* fff_B = (const float*)d_in[12];
    const float* ffp_W = (const float*)d_in[13];
    const float* ffp_A = (const float*)d_in[14];
    const float* ffp_B = (const float*)d_in[15];
    float* h = (float*)d_out;

    copy4_kernel<<<(NTOK * DM / 4 + 255) / 256, 256>>>((const float4*)x, (float4*)h,
                                                       NTOK * DM / 4);
    for (int it = 0; it < 4; ++it) {
        rmsnorm_kernel<<<NTOK, 256>>>(h);
        bx_mma<64><<<NTOK / 128, 256>>>(fg_B, gu_B, 2048, 0);
        gate_update_mma<<<dim3(NTOK / 64, 8), 256>>>(fg_W, gu_W, fg_A, gu_A, h);
    }
    rmsnorm_kernel<<<NTOK, 256>>>(h);
    bx_mma<64><<<NTOK / 128, 256>>>(ffg_B, fff_B, 1024, 1);
    ff_mma<<<dim3(NTOK / 64, 8, 3), 256>>>(ffg_W, fff_W, ffg_A, fff_A);
    bx_mma<32><<<NTOK / 128, 256>>>(ffp_B, ffp_B, 2816, 2);
    ffp_mma<<<dim3(NTOK / 64, 8), 256>>>(ffp_W, ffp_A, h);
}